// round 1
// baseline (speedup 1.0000x reference)
#include <cuda_runtime.h>
#include <cstddef>

namespace {

constexpr int B = 8, T = 2048, H = 256, L = 16;
constexpr int S = 32;                 // t-strip length per block
constexpr int WARPS = 4;              // warp g owns l in [4g, 4g+3]
constexpr int THREADS = WARPS * 32;
constexpr int STRIPS_PER_B = T / S;   // 64
constexpr int NBLOCKS = B * STRIPS_PER_B;  // 512
constexpr int NSTEPS = ((S + 16 + 4) / 5) * 5;  // 50 (steps padded to multiple of 5)

struct R8 { float v[8]; };

// Load 8 consecutive floats of row `row` (this lane's H-slice); zeros when OOB
// (implements the reference's zero padding for t-l < 0 and t+L >= T).
__device__ __forceinline__ R8 load_row8(const float* __restrict__ base, int row, int hbase) {
  R8 r;
  if ((unsigned)row < (unsigned)T) {
    const float4* p = reinterpret_cast<const float4*>(base + (size_t)row * H + hbase);
    float4 a = p[0];
    float4 b = p[1];
    r.v[0] = a.x; r.v[1] = a.y; r.v[2] = a.z; r.v[3] = a.w;
    r.v[4] = b.x; r.v[5] = b.y; r.v[6] = b.z; r.v[7] = b.w;
  } else {
#pragma unroll
    for (int j = 0; j < 8; j++) r.v[j] = 0.f;
  }
  return r;
}

__global__ __launch_bounds__(THREADS)
void ffm_kernel(const float* __restrict__ logits,
                const float* __restrict__ end_w,
                const float* __restrict__ whole_w,
                const float* __restrict__ relay_w,
                const float* __restrict__ relay_b,
                const float* __restrict__ length_bias,
                float* __restrict__ out,
                float* __restrict__ relay_out) {
  const int strip = blockIdx.x;
  const int b     = strip / STRIPS_PER_B;
  const int s0    = (strip % STRIPS_PER_B) * S;
  const int g     = threadIdx.x >> 5;   // warp id: l in [4g, 4g+3]
  const int lane  = threadIdx.x & 31;
  const int hbase = lane * 8;           // this lane's 8-float H slice

  // Weights held in registers for the whole strip.
  float w[4][8], ew[8], rw[8], bias[4];
#pragma unroll
  for (int k = 0; k < 4; k++) {
#pragma unroll
    for (int j = 0; j < 8; j++) w[k][j] = whole_w[(4 * g + k) * H + hbase + j];
    bias[k] = length_bias[4 * g + k];
  }
#pragma unroll
  for (int j = 0; j < 8; j++) {
    ew[j] = end_w[hbase + j];
    rw[j] = relay_w[hbase + j];
  }
  const float rb = relay_b[0];

  const float* lb = logits + (size_t)b * T * H;

  // 5-row register window. Row (s0 + u - 4g) is loaded at step u into slot (u mod 5).
  // So at step u (u == p mod 5), row r-4g-k lives in slot (p + 5 - k) % 5.
  R8 Wn[5];
#pragma unroll
  for (int k = 1; k <= 4; k++)  // prefill slots for "steps" u = -1..-4
    Wn[(5 - k) % 5] = load_row8(lb, s0 - 4 * g - k, hbase);

  for (int u0 = 0; u0 < NSTEPS; u0 += 5) {
#pragma unroll
    for (int p = 0; p < 5; p++) {
      const int u = u0 + p;
      const int r = s0 + u;

      Wn[p]  = load_row8(lb, r - 4 * g, hbase);  // advance window
      R8 cur = load_row8(lb, r, hbase);          // row t (and relay's row t+16)

      if (u < S) {  // whole/end outputs for t = r
        float acc0 = 0.f, acc1 = 0.f, acc2 = 0.f, acc3 = 0.f, e = 0.f;
#pragma unroll
        for (int j = 0; j < 8; j++) {
          const float c = cur.v[j];
          e    = fmaf(c, ew[j], e);
          acc0 = fmaf(fmaxf(c, Wn[p].v[j]),           w[0][j], acc0);  // l = 4g
          acc1 = fmaf(fmaxf(c, Wn[(p + 4) % 5].v[j]), w[1][j], acc1);  // l = 4g+1
          acc2 = fmaf(fmaxf(c, Wn[(p + 3) % 5].v[j]), w[2][j], acc2);  // l = 4g+2
          acc3 = fmaf(fmaxf(c, Wn[(p + 2) % 5].v[j]), w[3][j], acc3);  // l = 4g+3
        }
#pragma unroll
        for (int s = 16; s > 0; s >>= 1) {
          acc0 += __shfl_xor_sync(0xffffffffu, acc0, s);
          acc1 += __shfl_xor_sync(0xffffffffu, acc1, s);
          acc2 += __shfl_xor_sync(0xffffffffu, acc2, s);
          acc3 += __shfl_xor_sync(0xffffffffu, acc3, s);
          e    += __shfl_xor_sync(0xffffffffu, e, s);
        }
        if (lane == 0) {
          float4 o;
          o.x = acc0 + e + bias[0];
          o.y = acc1 + e + bias[1];
          o.z = acc2 + e + bias[2];
          o.w = acc3 + e + bias[3];
          *reinterpret_cast<float4*>(out + (size_t)(b * T + r) * L + 4 * g) = o;
        }
      }

      // Relay for t = r - 16 (warp 3's window reaches row r-16 at slot (p+1)%5).
      if (g == 3 && u >= 16 && u < S + 16) {
        float rel = 0.f;
#pragma unroll
        for (int j = 0; j < 8; j++)
          rel = fmaf(fmaxf(cur.v[j], Wn[(p + 1) % 5].v[j]), rw[j], rel);
#pragma unroll
        for (int s = 16; s > 0; s >>= 1)
          rel += __shfl_xor_sync(0xffffffffu, rel, s);
        if (lane == 0) relay_out[(size_t)b * T + (r - 16)] = rel + rb;
      }
    }
  }
}

}  // namespace

extern "C" void kernel_launch(void* const* d_in, const int* in_sizes, int n_in,
                              void* d_out, int out_size) {
  const float* logits  = (const float*)d_in[0];
  const float* end_w   = (const float*)d_in[1];
  const float* whole_w = (const float*)d_in[2];
  const float* relay_w = (const float*)d_in[3];
  const float* relay_b = (const float*)d_in[4];
  const float* lbias   = (const float*)d_in[5];

  float* out   = (float*)d_out;                    // [B, T, L]
  float* relay = out + (size_t)B * T * L;          // [B, T] appended

  ffm_kernel<<<NBLOCKS, THREADS>>>(logits, end_w, whole_w, relay_w, relay_b,
                                   lbias, out, relay);
}